// round 9
// baseline (speedup 1.0000x reference)
#include <cuda_runtime.h>
#include <cstdint>

// out[i, 0:32] = weight[b[i], 0:32] (fp32), out[0, :] = 0.
// N = 1e6 rows, 8 float4/row, 128 MB output vs 126 MB L2.
//
// Two-kernel graph:
//  1) discard_l2: drops every 128B line of the output from L2 WITHOUT
//     writeback (discard.global.L2). The previous replay's dirty copies
//     are dead data (fully overwritten this replay), so this removes
//     ~72 MB/launch of eviction writebacks from the LTS/DRAM path.
//  2) gather_rows: plain write-back float4 stores into a now-clean L2;
//     store misses evict clean lines (no writeback traffic).

static constexpr int Y_DIM = 32;
static constexpr int VEC_PER_ROW = Y_DIM / 4;   // 8
static constexpr int TPB = 256;
static constexpr int VPT = 4;                    // float4 per thread
static constexpr int TILE = TPB * VPT;           // 1024 vec4 per block

// ---------------- discard kernel ----------------
static constexpr int LINES_PER_THREAD = 4;
static constexpr int DISCARD_TPB = 256;

__global__ __launch_bounds__(DISCARD_TPB) void discard_l2(
    char* __restrict__ base, long long n_lines)
{
    long long t = (long long)blockIdx.x * (DISCARD_TPB * LINES_PER_THREAD)
                + threadIdx.x;
    #pragma unroll
    for (int k = 0; k < LINES_PER_THREAD; k++) {
        long long line = t + (long long)k * DISCARD_TPB;
        if (line < n_lines) {
            asm volatile("discard.global.L2 [%0], 128;"
                         :: "l"(base + line * 128) : "memory");
        }
    }
}

// ---------------- gather kernel ----------------
__global__ __launch_bounds__(TPB) void gather_rows(
    const int* __restrict__ b,          // [N]
    const float* __restrict__ weight,   // [64, 32]
    float4* __restrict__ out,           // [N*8] float4
    int n_vec)
{
    const float4* __restrict__ w4 = reinterpret_cast<const float4*>(weight);

    int base = blockIdx.x * TILE + threadIdx.x;

    if (blockIdx.x != 0) {
        int  v[VPT];
        int  bi[VPT];
        bool ok[VPT];
        #pragma unroll
        for (int k = 0; k < VPT; k++) {
            v[k]  = base + k * TPB;
            ok[k] = v[k] < n_vec;
            bi[k] = ok[k] ? __ldg(&b[v[k] >> 3]) : 0;
        }
        float4 val[VPT];
        #pragma unroll
        for (int k = 0; k < VPT; k++)
            val[k] = __ldg(&w4[bi[k] * VEC_PER_ROW + (v[k] & 7)]);
        #pragma unroll
        for (int k = 0; k < VPT; k++)
            if (ok[k]) out[v[k]] = val[k];
    } else {
        // Block 0: same flow plus the out[0,:] = 0 override.
        int  v[VPT];
        int  bi[VPT];
        #pragma unroll
        for (int k = 0; k < VPT; k++) {
            v[k]  = base + k * TPB;
            bi[k] = __ldg(&b[v[k] >> 3]);
        }
        float4 val[VPT];
        #pragma unroll
        for (int k = 0; k < VPT; k++) {
            val[k] = __ldg(&w4[bi[k] * VEC_PER_ROW + (v[k] & 7)]);
            if (v[k] < VEC_PER_ROW) val[k] = make_float4(0.f, 0.f, 0.f, 0.f);
        }
        #pragma unroll
        for (int k = 0; k < VPT; k++)
            out[v[k]] = val[k];
    }
}

extern "C" void kernel_launch(void* const* d_in, const int* in_sizes, int n_in,
                              void* d_out, int out_size) {
    const int*   b      = (const int*)d_in[0];
    const float* weight = (const float*)d_in[1];
    float4*      out    = (float4*)d_out;

    int n     = in_sizes[0];          // N rows
    int n_vec = n * VEC_PER_ROW;      // 8M float4

    // 1) Drop the previous replay's dead dirty lines (no writeback).
    //    Only discard lines fully inside the output buffer.
    long long total_bytes = (long long)out_size * sizeof(float);
    long long n_lines = total_bytes / 128;
    if (n_lines > 0) {
        long long per_block = (long long)DISCARD_TPB * LINES_PER_THREAD;
        int dblocks = (int)((n_lines + per_block - 1) / per_block);
        discard_l2<<<dblocks, DISCARD_TPB>>>((char*)d_out, n_lines);
    }

    // 2) Gather with default write-back stores into a clean L2.
    int blocks = (n_vec + TILE - 1) / TILE;
    gather_rows<<<blocks, TPB>>>(b, weight, out, n_vec);
}

// round 10
// speedup vs baseline: 1.0883x; 1.0883x over previous
#include <cuda_runtime.h>
#include <cstdint>

// out[i, 0:32] = weight[b[i], 0:32] (fp32), out[0, :] = 0.
// N = 1e6 rows, 128 B per row, 128 MB output.
//
// TMA-store variant: gather 256 rows (32 KB) into SMEM per block
// (conflict-free: 8 threads per row, consecutive 16B STS), then one
// cp.async.bulk.global.shared::cta writes the tile to GMEM as full
// 128B lines — bypassing the per-sector STG store-miss path that has
// pinned every STG-based variant at ~5.9 TB/s.

static constexpr int Y_DIM = 32;
static constexpr int VEC_PER_ROW = Y_DIM / 4;       // 8 float4 per row
static constexpr int TPB = 256;
static constexpr int ROWS_PER_BLOCK = 256;          // 32 KB tile
static constexpr int VECS_PER_BLOCK = ROWS_PER_BLOCK * VEC_PER_ROW;  // 2048
static constexpr int ITERS = VECS_PER_BLOCK / TPB;  // 8

__global__ __launch_bounds__(TPB) void gather_rows_tma(
    const int* __restrict__ b,          // [N]
    const float* __restrict__ weight,   // [64, 32]
    float* __restrict__ out,            // [N*32]
    int n_rows)
{
    __shared__ alignas(128) float4 tile[VECS_PER_BLOCK];

    const float4* __restrict__ w4 = reinterpret_cast<const float4*>(weight);

    int row0  = blockIdx.x * ROWS_PER_BLOCK;
    int nrows = n_rows - row0;
    if (nrows > ROWS_PER_BLOCK) nrows = ROWS_PER_BLOCK;

    // Gather into SMEM. v = vec4 index within tile; 8 consecutive lanes
    // share one row (index load broadcasts), STS addresses are
    // consecutive 16B across the warp -> conflict-free.
    #pragma unroll
    for (int it = 0; it < ITERS; it++) {
        int v  = it * TPB + threadIdx.x;
        int rl = v >> 3;                 // row within tile
        int row = row0 + rl;
        if (rl < nrows) {
            int bi = __ldg(&b[row]);
            float4 val = __ldg(&w4[bi * VEC_PER_ROW + (v & 7)]);
            if (row == 0) val = make_float4(0.f, 0.f, 0.f, 0.f);
            tile[v] = val;
        }
    }
    __syncthreads();

    // One thread issues the bulk SMEM->GMEM copy for the whole tile.
    if (threadIdx.x == 0) {
        uint32_t saddr;
        asm("{ .reg .u64 t; cvta.to.shared.u64 t, %1; cvt.u32.u64 %0, t; }"
            : "=r"(saddr) : "l"(tile));
        float* gdst = out + (size_t)row0 * Y_DIM;
        int    bytes = nrows * 128;
        asm volatile(
            "cp.async.bulk.global.shared::cta.bulk_group [%0], [%1], %2;"
            :: "l"(gdst), "r"(saddr), "r"(bytes) : "memory");
        asm volatile("cp.async.bulk.commit_group;" ::: "memory");
        asm volatile("cp.async.bulk.wait_group 0;" ::: "memory");
    }
}

extern "C" void kernel_launch(void* const* d_in, const int* in_sizes, int n_in,
                              void* d_out, int out_size) {
    const int*   b      = (const int*)d_in[0];
    const float* weight = (const float*)d_in[1];
    float*       out    = (float*)d_out;

    int n_rows = in_sizes[0];   // N
    int blocks = (n_rows + ROWS_PER_BLOCK - 1) / ROWS_PER_BLOCK;
    gather_rows_tma<<<blocks, TPB>>>(b, weight, out, n_rows);
}

// round 12
// speedup vs baseline: 1.2527x; 1.1511x over previous
#include <cuda_runtime.h>
#include <cstdint>

// out[i, 0:32] = weight[b[i], 0:32] (fp32), out[0, :] = 0.
// N = 1e6 rows, 32 floats/row = 4 octs (32B) per row; 128 MB output.
//
// Final form. Evidence from R2-R10: single-launch time is pinned at
// ~21.6us by the path-independent LTS cap for the 128MB store stream
// (stcs / default / v8 / L2-pin / discard / TMA all equal). The bench
// (graph-replay steady state) separates on store policy: evict_first
// streaming stores save ~2.9us/launch vs default. This kernel combines
// the two proven-best elements, never before together:
//   - st.global.L2::evict_first.v8.b32 (256-bit streaming stores; the
//     evict hint is only ptxas-legal on v8)
//   - VPT=4 octs/thread, phased index->load->store for MLP=4
//   - row-0 zeroing hoisted so only block 0 evaluates it

static constexpr int OCT_PER_ROW = 4;   // 32 floats / 8
static constexpr int TPB  = 256;
static constexpr int VPT  = 4;          // octs per thread
static constexpr int TILE = TPB * VPT;  // 1024 octs per block

__device__ __forceinline__ void ldg256(const float* p, uint32_t r[8]) {
    asm volatile("ld.global.nc.v8.b32 {%0,%1,%2,%3,%4,%5,%6,%7}, [%8];"
                 : "=r"(r[0]), "=r"(r[1]), "=r"(r[2]), "=r"(r[3]),
                   "=r"(r[4]), "=r"(r[5]), "=r"(r[6]), "=r"(r[7])
                 : "l"(p));
}

__device__ __forceinline__ void st256_stream(float* p, const uint32_t r[8]) {
    asm volatile("st.global.L2::evict_first.v8.b32 [%0], {%1,%2,%3,%4,%5,%6,%7,%8};"
                 :: "l"(p),
                    "r"(r[0]), "r"(r[1]), "r"(r[2]), "r"(r[3]),
                    "r"(r[4]), "r"(r[5]), "r"(r[6]), "r"(r[7])
                 : "memory");
}

__global__ __launch_bounds__(TPB) void gather_rows_v8s(
    const int* __restrict__ b,          // [N]
    const float* __restrict__ weight,   // [64, 32]
    float* __restrict__ out,            // [N*32]
    int n_oct)                          // N * 4
{
    int base = blockIdx.x * TILE + threadIdx.x;

    if (blockIdx.x != 0) {
        int  v[VPT];
        int  bi[VPT];
        bool ok[VPT];
        // Phase 1: indices (4 lanes broadcast per row)
        #pragma unroll
        for (int k = 0; k < VPT; k++) {
            v[k]  = base + k * TPB;
            ok[k] = v[k] < n_oct;
            bi[k] = ok[k] ? __ldg(&b[v[k] >> 2]) : 0;
        }
        // Phase 2: weight octs (8 KB table, L1-resident)
        uint32_t val[VPT][8];
        #pragma unroll
        for (int k = 0; k < VPT; k++)
            ldg256(weight + bi[k] * 32 + (v[k] & 3) * 8, val[k]);
        // Phase 3: 256-bit streaming stores (warp = 1KB contiguous)
        #pragma unroll
        for (int k = 0; k < VPT; k++)
            if (ok[k]) st256_stream(out + (size_t)v[k] * 8, val[k]);
    } else {
        // Block 0: identical flow plus out[0,:] = 0 override.
        int v[VPT];
        int bi[VPT];
        #pragma unroll
        for (int k = 0; k < VPT; k++) {
            v[k]  = base + k * TPB;
            bi[k] = __ldg(&b[v[k] >> 2]);
        }
        uint32_t val[VPT][8];
        #pragma unroll
        for (int k = 0; k < VPT; k++) {
            ldg256(weight + bi[k] * 32 + (v[k] & 3) * 8, val[k]);
            if (v[k] < OCT_PER_ROW) {
                #pragma unroll
                for (int j = 0; j < 8; j++) val[k][j] = 0u;
            }
        }
        #pragma unroll
        for (int k = 0; k < VPT; k++)
            st256_stream(out + (size_t)v[k] * 8, val[k]);
    }
}

extern "C" void kernel_launch(void* const* d_in, const int* in_sizes, int n_in,
                              void* d_out, int out_size) {
    const int*   b      = (const int*)d_in[0];
    const float* weight = (const float*)d_in[1];
    float*       out    = (float*)d_out;

    int n     = in_sizes[0];          // N rows
    int n_oct = n * OCT_PER_ROW;      // 4M octs

    int blocks = (n_oct + TILE - 1) / TILE;
    gather_rows_v8s<<<blocks, TPB>>>(b, weight, out, n_oct);
}